// round 11
// baseline (speedup 1.0000x reference)
#include <cuda_runtime.h>
#include <math_constants.h>

#define BB 4
#define VV 4096
#define FF 64
#define SS 4
#define KN 39            // neighbours kept (K_NEIGHBOURS=40 includes self)
#define OUTF 64
#define TPB 128
#define BND_MAX 64

// Scratch (device globals; no allocation allowed)
__device__ float g_coords[BB * VV * 4];     // (b, v, 4) — float4-aligned rows
__device__ float g_feats[BB * VV * FF];     // (b, v, 64)

// ---------------------------------------------------------------------------
// Kernel 1: coords = x@Ws + bs, feats = x@Wf + bf
// ---------------------------------------------------------------------------
__global__ void __launch_bounds__(64) prep_kernel(
    const float* __restrict__ x,
    const float* __restrict__ Wf, const float* __restrict__ bf,
    const float* __restrict__ Ws, const float* __restrict__ bs)
{
    const int vtx = blockIdx.x;        // 0 .. B*V-1
    const int f   = threadIdx.x;       // 0 .. 63
    __shared__ float sx[FF];
    sx[f] = x[vtx * FF + f];
    __syncthreads();

    float acc = bf[f];
#pragma unroll
    for (int k = 0; k < FF; ++k)
        acc = fmaf(sx[k], Wf[k * FF + f], acc);
    g_feats[vtx * FF + f] = acc;

    if (f < SS) {
        float c = bs[f];
#pragma unroll
        for (int k = 0; k < FF; ++k)
            c = fmaf(sx[k], Ws[k * SS + f], c);
        g_coords[vtx * 4 + f] = c;
    }
}

// ---------------------------------------------------------------------------
// Kernel 2: per-query kNN select (two-level radix histogram: exponent byte
// with warp-aggregated atomics, then mantissa-top-8 over cached d2) +
// weighted max/mean aggregation + output GEMM + tanh. One block per query.
// ---------------------------------------------------------------------------
__global__ void __launch_bounds__(TPB, 10) grav_kernel(
    const float* __restrict__ x,
    const float* __restrict__ Wo, const float* __restrict__ bo,
    float* __restrict__ out)
{
    const int v    = blockIdx.x;       // vertex within batch
    const int b    = blockIdx.y;       // batch
    const int tid  = threadIdx.x;
    const int lane = tid & 31;
    const int base = b * VV;

    __shared__ float4 s_d2v[VV / 4];           // 16 KB (float4 view of d2)
    __shared__ unsigned s_hist[256];           // 1 KB (reused for both levels)
    __shared__ float s_cat[192];               // [xq(64) | max(64) | mean(64)]
    __shared__ int   s_nidx[KN + 1];
    __shared__ float s_nd2[KN + 1];
    __shared__ float s_nw[KN + 1];
    __shared__ float s_mx2[64], s_sm2[64], s_gemm[64];
    __shared__ unsigned long long s_bnd[BND_MAX];
    __shared__ unsigned long long s_red[4];
    __shared__ unsigned long long s_win;
    __shared__ int s_cdef, s_cbnd, s_bkey, s_c;
    __shared__ int s_wt[4];

    float* s_d2 = reinterpret_cast<float*>(s_d2v);

    const float4* cb = reinterpret_cast<const float4*>(g_coords) + base;
    const float4 cq = cb[v];

    if (tid < FF) s_cat[tid] = x[(base + v) * FF + tid];
    reinterpret_cast<uint2*>(s_hist)[tid] = make_uint2(0u, 0u);
    if (tid == 0) { s_cdef = 0; s_cbnd = 0; }
    __syncthreads();

    // ---- Pass 1: distances (cached in smem) + exponent-byte histogram.
    //      match_any aggregation: lanes sharing an exponent merge into one
    //      ATOMS (d2 spans ~8-12 exponents -> ~4x fewer atomic lane-ops).
    //      Self d2 == 0 exactly (bin 0); patched out afterwards. ----
#pragma unroll 4
    for (int i = tid; i < VV; i += TPB) {
        float4 cu = cb[i];
        float dx = cq.x - cu.x, dy = cq.y - cu.y;
        float dz = cq.z - cu.z, dw = cq.w - cu.w;
        float d2 = fmaf(dx, dx, fmaf(dy, dy, fmaf(dz, dz, dw * dw)));
        s_d2[i] = d2;
        unsigned key = __float_as_uint(d2) >> 23;
        unsigned peers = __match_any_sync(0xffffffffu, key);
        if (lane == __ffs(peers) - 1)
            atomicAdd(&s_hist[key], (unsigned)__popc(peers));
    }
    __syncthreads();
    if (tid == 0) {
        s_hist[0] -= 1u;                        // drop self (d2=0 -> exp 0)
        s_d2[v] = CUDART_INF_F;
    }
    __syncthreads();

    // ---- Scan level 1: crossing exponent bin + prefix count ----
    {
        uint2 a = reinterpret_cast<uint2*>(s_hist)[tid];
        int h0 = (int)a.x, h1 = (int)a.y;
        int lsum = h0 + h1;
        int incl = lsum;
#pragma unroll
        for (int o = 1; o < 32; o <<= 1) {
            int n = __shfl_up_sync(0xffffffffu, incl, o);
            if (lane >= o) incl += n;
        }
        if (lane == 31) s_wt[tid >> 5] = incl;
        __syncthreads();
        int wprefix = 0;
        const int wid = tid >> 5;
        if (wid > 0) wprefix += s_wt[0];
        if (wid > 1) wprefix += s_wt[1];
        if (wid > 2) wprefix += s_wt[2];
        int excl = wprefix + incl - lsum;
        if (excl < KN && excl + lsum >= KN) {
            if (excl + h0 >= KN) { s_bkey = 2 * tid;     s_c = excl; }
            else                 { s_bkey = 2 * tid + 1; s_c = excl + h0; }
        }
        __syncthreads();
    }
    const int estar = s_bkey;
    const int c1 = s_c;
    const unsigned ulo_e = (unsigned)estar << 23;
    const unsigned uhi_e = (unsigned)(estar + 1) << 23;

    // ---- Level 2: mantissa-top-8 histogram of boundary-exponent members,
    //      swept over cached d2 (cheap LDS, few hundred atomics). ----
    reinterpret_cast<uint2*>(s_hist)[tid] = make_uint2(0u, 0u);
    __syncthreads();
    for (int it = 0; it < VV / 4 / TPB; ++it) {
        float4 d4 = s_d2v[it * TPB + tid];
#pragma unroll
        for (int e = 0; e < 4; ++e) {
            unsigned u = __float_as_uint(
                (e == 0) ? d4.x : (e == 1) ? d4.y : (e == 2) ? d4.z : d4.w);
            if (u >= ulo_e && u < uhi_e)
                atomicAdd(&s_hist[(u >> 15) & 0xFFu], 1u);
        }
    }
    __syncthreads();

    // ---- Scan level 2: crossing mantissa bin (need = KN - c1) ----
    {
        const int need = KN - c1;
        uint2 a = reinterpret_cast<uint2*>(s_hist)[tid];
        int h0 = (int)a.x, h1 = (int)a.y;
        int lsum = h0 + h1;
        int incl = lsum;
#pragma unroll
        for (int o = 1; o < 32; o <<= 1) {
            int n = __shfl_up_sync(0xffffffffu, incl, o);
            if (lane >= o) incl += n;
        }
        if (lane == 31) s_wt[tid >> 5] = incl;
        __syncthreads();
        int wprefix = 0;
        const int wid = tid >> 5;
        if (wid > 0) wprefix += s_wt[0];
        if (wid > 1) wprefix += s_wt[1];
        if (wid > 2) wprefix += s_wt[2];
        int excl = wprefix + incl - lsum;
        if (excl < need && excl + lsum >= need) {
            if (excl + h0 >= need) { s_bkey = 2 * tid;     s_c = c1 + excl; }
            else                   { s_bkey = 2 * tid + 1; s_c = c1 + excl + h0; }
        }
        __syncthreads();
    }
    const int c = s_c;                          // definite count (< 39)
    const unsigned bprefix = ((unsigned)estar << 8) | (unsigned)s_bkey;
    const unsigned lo_u = bprefix << 15;        // exact 17-bit prefix bounds
    const unsigned hi_u = (bprefix + 1u) << 15;

    // ---- Gather pass: definite + boundary (vectorized, 2 compares) ----
    for (int it = 0; it < VV / 4 / TPB; ++it) {
        int i4 = it * TPB + tid;
        float4 d4 = s_d2v[i4];
        int ib = i4 * 4;
#pragma unroll
        for (int e = 0; e < 4; ++e) {
            float dv = (e == 0) ? d4.x : (e == 1) ? d4.y : (e == 2) ? d4.z : d4.w;
            unsigned u = __float_as_uint(dv);
            if (u < hi_u) {
                if (u < lo_u) {
                    int pos = atomicAdd(&s_cdef, 1);
                    s_nidx[pos] = ib + e;
                    s_nd2[pos] = dv;
                } else {
                    int pos = atomicAdd(&s_cbnd, 1);
                    if (pos < BND_MAX)
                        s_bnd[pos] = ((unsigned long long)u << 32)
                                     | (unsigned)(ib + e);
                }
            }
        }
    }
    __syncthreads();

    const int m = s_cbnd;
    const int r = KN - c;                       // boundary picks needed (>=1)

    if (m <= BND_MAX) {
        // Extract r smallest by (d2, idx) from the small boundary list.
        for (int j = 0; j < r; ++j) {
            unsigned long long lk = (tid < m) ? s_bnd[tid]
                                              : 0xFFFFFFFFFFFFFFFFULL;
#pragma unroll
            for (int o = 16; o > 0; o >>= 1) {
                unsigned long long oth = __shfl_down_sync(0xffffffffu, lk, o);
                lk = (oth < lk) ? oth : lk;
            }
            if (lane == 0) s_red[tid >> 5] = lk;
            __syncthreads();
            if (tid == 0) {
                unsigned long long w0 = s_red[0];
                if (s_red[1] < w0) w0 = s_red[1];
                if (s_red[2] < w0) w0 = s_red[2];
                if (s_red[3] < w0) w0 = s_red[3];
                s_win = w0;
                s_nidx[c + j] = (int)(w0 & 0xFFFFFFFFULL);
                s_nd2[c + j]  = __uint_as_float((unsigned)(w0 >> 32));
            }
            __syncthreads();
            if (tid < m && s_bnd[tid] == s_win)
                s_bnd[tid] = 0xFFFFFFFFFFFFFFFFULL;
            __syncthreads();
        }
    } else {
        // Degenerate fallback (massive tie bin): exact extraction over s_d2.
        for (int j = 0; j < r; ++j) {
            unsigned long long lk = 0xFFFFFFFFFFFFFFFFULL;
            for (int i = tid; i < VV; i += TPB) {
                unsigned u = __float_as_uint(s_d2[i]);
                if (u >= lo_u && u < hi_u) {
                    unsigned long long key =
                        ((unsigned long long)u << 32) | (unsigned)i;
                    if (key < lk) lk = key;
                }
            }
#pragma unroll
            for (int o = 16; o > 0; o >>= 1) {
                unsigned long long oth = __shfl_down_sync(0xffffffffu, lk, o);
                lk = (oth < lk) ? oth : lk;
            }
            if (lane == 0) s_red[tid >> 5] = lk;
            __syncthreads();
            if (tid == 0) {
                unsigned long long w0 = s_red[0];
                if (s_red[1] < w0) w0 = s_red[1];
                if (s_red[2] < w0) w0 = s_red[2];
                if (s_red[3] < w0) w0 = s_red[3];
                int widx = (int)(w0 & 0xFFFFFFFFULL);
                s_nidx[c + j] = widx;
                s_nd2[c + j]  = __uint_as_float((unsigned)(w0 >> 32));
                s_d2[widx] = __uint_as_float(0xFFFFFFFFu); // consumed marker
            }
            __syncthreads();
        }
    }

    // ---- Weights ----
    if (tid < KN)
        s_nw[tid] = expf(-10.0f * fabsf(s_nd2[tid]));
    __syncthreads();

    // ---- Weighted aggregation: max + mean over 39; constant trip counts ----
    {
        const float* fb = g_feats + (size_t)base * FF;
        const int f = tid & 63;
        const int half = tid >> 6;
        float mx = -CUDART_INF_F;
        float sm = 0.0f;
        if (half) {
#pragma unroll 4
            for (int j = 20; j < KN; ++j) {
                float val = fb[s_nidx[j] * FF + f] * s_nw[j];
                mx = fmaxf(mx, val);
                sm += val;
            }
            s_mx2[f] = mx; s_sm2[f] = sm;
        } else {
#pragma unroll 4
            for (int j = 0; j < 20; ++j) {
                float val = fb[s_nidx[j] * FF + f] * s_nw[j];
                mx = fmaxf(mx, val);
                sm += val;
            }
        }
        __syncthreads();
        if (!half) {
            mx = fmaxf(mx, s_mx2[f]);
            sm += s_sm2[f];
            s_cat[FF + f]       = mx;
            s_cat[2 * FF + f]   = sm * (1.0f / KN);
        }
        __syncthreads();
    }

    // ---- Output GEMM: s_cat (192) @ Wo (192x64) + bo, tanh.
    //      Coalesced Wo reads (lanes consecutive in o); k split 96/96. ----
    {
        const int o = tid & 63;
        float acc = 0.0f;
        if (tid < 64) {
#pragma unroll
            for (int k = 0; k < 96; ++k)
                acc = fmaf(s_cat[k], Wo[k * OUTF + o], acc);
        } else {
#pragma unroll
            for (int k = 96; k < 192; ++k)
                acc = fmaf(s_cat[k], Wo[k * OUTF + o], acc);
            s_gemm[o] = acc;
        }
        __syncthreads();
        if (tid < 64)
            out[(base + v) * OUTF + o] = tanhf(acc + s_gemm[o] + bo[o]);
    }
}

// ---------------------------------------------------------------------------
extern "C" void kernel_launch(void* const* d_in, const int* in_sizes, int n_in,
                              void* d_out, int out_size)
{
    const float* x  = (const float*)d_in[0];
    const float* Wf = (const float*)d_in[1];
    const float* bf = (const float*)d_in[2];
    const float* Ws = (const float*)d_in[3];
    const float* bs = (const float*)d_in[4];
    const float* Wo = (const float*)d_in[5];
    const float* bo = (const float*)d_in[6];
    float* out = (float*)d_out;

    prep_kernel<<<BB * VV, 64>>>(x, Wf, bf, Ws, bs);

    dim3 grid(VV, BB);
    grav_kernel<<<grid, TPB>>>(x, Wo, bo, out);
}

// round 14
// speedup vs baseline: 1.3635x; 1.3635x over previous
#include <cuda_runtime.h>
#include <math_constants.h>

#define BB 4
#define VV 4096
#define FF 64
#define SS 4
#define KN 39            // neighbours kept (K_NEIGHBOURS=40 includes self)
#define OUTF 64
#define TPB 256          // 2 queries x 128 threads
#define BND_MAX 64
#define NB 512           // histogram bins
#define KBASE 760        // (u>>20) offset: covers biased exponents 95..158

// Scratch (device globals; no allocation allowed)
__device__ float g_coords[BB * VV * 4];     // (b, v, 4) — float4-aligned rows
__device__ float g_feats[BB * VV * FF];     // (b, v, 64)

// ---------------------------------------------------------------------------
// Kernel 1: coords = x@Ws + bs, feats = x@Wf + bf
// ---------------------------------------------------------------------------
__global__ void __launch_bounds__(64) prep_kernel(
    const float* __restrict__ x,
    const float* __restrict__ Wf, const float* __restrict__ bf,
    const float* __restrict__ Ws, const float* __restrict__ bs)
{
    const int vtx = blockIdx.x;        // 0 .. B*V-1
    const int f   = threadIdx.x;       // 0 .. 63
    __shared__ float sx[FF];
    sx[f] = x[vtx * FF + f];
    __syncthreads();

    float acc = bf[f];
#pragma unroll
    for (int k = 0; k < FF; ++k)
        acc = fmaf(sx[k], Wf[k * FF + f], acc);
    g_feats[vtx * FF + f] = acc;

    if (f < SS) {
        float c = bs[f];
#pragma unroll
        for (int k = 0; k < FF; ++k)
            c = fmaf(sx[k], Ws[k * SS + f], c);
        g_coords[vtx * 4 + f] = c;
    }
}

__device__ __forceinline__ int d2_key(unsigned u)
{
    int p = (int)(u >> 20) - KBASE;
    p = max(p, 0);
    return min(p, NB - 1);
}

// Named barrier for one 128-thread half (query q uses id q+1).
__device__ __forceinline__ void barq(int q)
{
    asm volatile("bar.sync %0, 128;" :: "r"(q + 1) : "memory");
}

// ---------------------------------------------------------------------------
// Kernel 2: TWO queries per block. Shared coord loads in pass 1; shared Wo
// lines in the output GEMM. Per-query select/aggregate runs in each
// 128-thread half, synchronized with named barriers.
// ---------------------------------------------------------------------------
__global__ void __launch_bounds__(TPB, 5) grav_kernel(
    const float* __restrict__ x,
    const float* __restrict__ Wo, const float* __restrict__ bo,
    float* __restrict__ out)
{
    const int v0   = blockIdx.x * 2;   // first query vertex of this block
    const int b    = blockIdx.y;       // batch
    const int tid  = threadIdx.x;
    const int lane = tid & 31;
    const int q    = tid >> 7;         // query half: 0 or 1
    const int wt   = tid & 127;        // thread index within half
    const int base = b * VV;

    __shared__ float4 s_d2v[2][VV / 4];        // 32 KB
    __shared__ unsigned s_hist[2][NB];         // 4 KB
    __shared__ float s_cat[2][192];            // [xq | max | mean] per query
    __shared__ int   s_nidx[2][KN + 1];
    __shared__ float s_nd2[2][KN + 1];
    __shared__ float s_nw[2][KN + 1];
    __shared__ float s_mx2[2][64], s_sm2[2][64];
    __shared__ float s_part[4][2][64];         // GEMM partials [kseg][q][o]
    __shared__ unsigned long long s_bnd[2][BND_MAX];
    __shared__ unsigned long long s_red[2][4];
    __shared__ unsigned long long s_win[2];
    __shared__ int s_cdef[2], s_cbnd[2], s_bkey[2], s_c[2];
    __shared__ int s_wsc[2][4];

    const float4* cb = reinterpret_cast<const float4*>(g_coords) + base;
    const float4 cqa = cb[v0];
    const float4 cqb = cb[v0 + 1];
    float* s_d2q = reinterpret_cast<float*>(s_d2v[q]);

    if (tid < 128)
        s_cat[tid >> 6][tid & 63] =
            x[(base + v0 + (tid >> 6)) * FF + (tid & 63)];
    reinterpret_cast<uint4*>(&s_hist[0][0])[tid] = make_uint4(0u, 0u, 0u, 0u);
    if (tid < 2) { s_cdef[tid] = 0; s_cbnd[tid] = 0; }
    __syncthreads();

    // ---- Pass 1: one coord load -> two distances + two histogram bumps.
    //      Self d2 == 0 exactly (bin 0); patched out afterwards. ----
    {
        float* da = reinterpret_cast<float*>(s_d2v[0]);
        float* db = reinterpret_cast<float*>(s_d2v[1]);
#pragma unroll 4
        for (int i = tid; i < VV; i += TPB) {
            float4 cu = cb[i];
            float ax = cqa.x - cu.x, ay = cqa.y - cu.y;
            float az = cqa.z - cu.z, aw = cqa.w - cu.w;
            float bx = cqb.x - cu.x, by = cqb.y - cu.y;
            float bz = cqb.z - cu.z, bw = cqb.w - cu.w;
            float d2a = fmaf(ax, ax, fmaf(ay, ay, fmaf(az, az, aw * aw)));
            float d2b = fmaf(bx, bx, fmaf(by, by, fmaf(bz, bz, bw * bw)));
            da[i] = d2a;
            db[i] = d2b;
            atomicAdd(&s_hist[0][d2_key(__float_as_uint(d2a))], 1u);
            atomicAdd(&s_hist[1][d2_key(__float_as_uint(d2b))], 1u);
        }
    }
    __syncthreads();
    if (tid < 2) {
        s_hist[tid][0]      -= 1u;              // remove self (d2=0 -> bin 0)
        s_hist[tid][NB - 1] += 1u;              // park self in top bin
        reinterpret_cast<float*>(s_d2v[tid])[v0 + tid] = CUDART_INF_F;
    }
    __syncthreads();

    // ---- Parallel scan, both histograms concurrently (half q scans q) ----
    {
        uint4 a = reinterpret_cast<const uint4*>(&s_hist[q][0])[wt];
        int h0 = (int)a.x, h1 = (int)a.y, h2 = (int)a.z, h3 = (int)a.w;
        int lsum = h0 + h1 + h2 + h3;
        int incl = lsum;
#pragma unroll
        for (int o = 1; o < 32; o <<= 1) {
            int n = __shfl_up_sync(0xffffffffu, incl, o);
            if (lane >= o) incl += n;
        }
        if (lane == 31) s_wsc[q][wt >> 5] = incl;
        __syncthreads();
        int wprefix = 0;
        const int wid = wt >> 5;
        if (wid > 0) wprefix += s_wsc[q][0];
        if (wid > 1) wprefix += s_wsc[q][1];
        if (wid > 2) wprefix += s_wsc[q][2];
        int excl = wprefix + incl - lsum;       // count before bin wt*4
        if (excl < KN && excl + lsum >= KN) {
            int cum = excl, bin = 4 * wt;
            if (cum + h0 < KN) { cum += h0; ++bin;
                if (cum + h1 < KN) { cum += h1; ++bin;
                    if (cum + h2 < KN) { cum += h2; ++bin; } } }
            s_bkey[q] = bin; s_c[q] = cum;
        }
        __syncthreads();
    }
    const int bkey = s_bkey[q];
    const int c = s_c[q];                       // definite count (< 39)
    const int vq = v0 + q;
    const unsigned lo_u = (bkey == 0) ? 0u
                        : ((unsigned)(bkey + KBASE) << 20);
    const unsigned hi_u = (bkey == NB - 1) ? 0xFFFFFFFFu
                        : ((unsigned)(bkey + 1 + KBASE) << 20);

    // ---- Gather (half q sweeps its own d2 array; 2 compares/cand) ----
    for (int it = 0; it < VV / 4 / 128; ++it) {
        int i4 = it * 128 + wt;
        float4 d4 = s_d2v[q][i4];
        int ib = i4 * 4;
#pragma unroll
        for (int e = 0; e < 4; ++e) {
            float dv = (e == 0) ? d4.x : (e == 1) ? d4.y : (e == 2) ? d4.z : d4.w;
            unsigned u = __float_as_uint(dv);
            if (u < hi_u) {
                if (u < lo_u) {
                    int pos = atomicAdd(&s_cdef[q], 1);
                    s_nidx[q][pos] = ib + e;
                    s_nd2[q][pos] = dv;
                } else if (ib + e != vq) {
                    int pos = atomicAdd(&s_cbnd[q], 1);
                    if (pos < BND_MAX)
                        s_bnd[q][pos] = ((unsigned long long)u << 32)
                                        | (unsigned)(ib + e);
                }
            }
        }
    }
    barq(q);

    const int m = s_cbnd[q];
    const int r = KN - c;                       // boundary picks needed (>=1)

    if (m <= BND_MAX) {
        // Extract r smallest by (d2, idx) from the small boundary list.
        for (int j = 0; j < r; ++j) {
            unsigned long long lk = (wt < m) ? s_bnd[q][wt]
                                             : 0xFFFFFFFFFFFFFFFFULL;
#pragma unroll
            for (int o = 16; o > 0; o >>= 1) {
                unsigned long long oth = __shfl_down_sync(0xffffffffu, lk, o);
                lk = (oth < lk) ? oth : lk;
            }
            if (lane == 0) s_red[q][wt >> 5] = lk;
            barq(q);
            if (wt == 0) {
                unsigned long long w0 = s_red[q][0];
                if (s_red[q][1] < w0) w0 = s_red[q][1];
                if (s_red[q][2] < w0) w0 = s_red[q][2];
                if (s_red[q][3] < w0) w0 = s_red[q][3];
                s_win[q] = w0;
                s_nidx[q][c + j] = (int)(w0 & 0xFFFFFFFFULL);
                s_nd2[q][c + j]  = __uint_as_float((unsigned)(w0 >> 32));
            }
            barq(q);
            if (wt < m && s_bnd[q][wt] == s_win[q])
                s_bnd[q][wt] = 0xFFFFFFFFFFFFFFFFULL;
            barq(q);
        }
    } else {
        // Degenerate fallback (massive tie bin): exact extraction over d2.
        for (int j = 0; j < r; ++j) {
            unsigned long long lk = 0xFFFFFFFFFFFFFFFFULL;
            for (int i = wt; i < VV; i += 128) {
                unsigned u = __float_as_uint(s_d2q[i]);
                if (u >= lo_u && u < hi_u && i != vq) {
                    unsigned long long key =
                        ((unsigned long long)u << 32) | (unsigned)i;
                    if (key < lk) lk = key;
                }
            }
#pragma unroll
            for (int o = 16; o > 0; o >>= 1) {
                unsigned long long oth = __shfl_down_sync(0xffffffffu, lk, o);
                lk = (oth < lk) ? oth : lk;
            }
            if (lane == 0) s_red[q][wt >> 5] = lk;
            barq(q);
            if (wt == 0) {
                unsigned long long w0 = s_red[q][0];
                if (s_red[q][1] < w0) w0 = s_red[q][1];
                if (s_red[q][2] < w0) w0 = s_red[q][2];
                if (s_red[q][3] < w0) w0 = s_red[q][3];
                int widx = (int)(w0 & 0xFFFFFFFFULL);
                s_nidx[q][c + j] = widx;
                s_nd2[q][c + j]  = __uint_as_float((unsigned)(w0 >> 32));
                s_d2q[widx] = __uint_as_float(0xFFFFFFFFu); // consumed
            }
            barq(q);
        }
    }

    // ---- Weights ----
    if (wt < KN)
        s_nw[q][wt] = expf(-10.0f * fabsf(s_nd2[q][wt]));
    barq(q);

    // ---- Weighted aggregation: max + mean over 39 (per query half) ----
    {
        const float* fb = g_feats + (size_t)base * FF;
        const int f = wt & 63;
        const int hj = wt >> 6;
        float mx = -CUDART_INF_F;
        float sm = 0.0f;
        if (hj) {
#pragma unroll 4
            for (int j = 20; j < KN; ++j) {
                float val = fb[s_nidx[q][j] * FF + f] * s_nw[q][j];
                mx = fmaxf(mx, val);
                sm += val;
            }
            s_mx2[q][f] = mx; s_sm2[q][f] = sm;
        } else {
#pragma unroll 4
            for (int j = 0; j < 20; ++j) {
                float val = fb[s_nidx[q][j] * FF + f] * s_nw[q][j];
                mx = fmaxf(mx, val);
                sm += val;
            }
        }
        barq(q);
        if (!hj) {
            mx = fmaxf(mx, s_mx2[q][f]);
            sm += s_sm2[q][f];
            s_cat[q][FF + f]     = mx;
            s_cat[q][2 * FF + f] = sm * (1.0f / KN);
        }
    }
    __syncthreads();

    // ---- Output GEMM, Wo shared across both queries:
    //      each Wo element is loaded ONCE per block and FMA'd into both
    //      queries' accumulators. 256 thr = 64 outputs x 4 k-segments. ----
    {
        const int o = tid & 63;
        const int kseg = tid >> 6;              // 0..3, 48 k each
        const int k0 = kseg * 48;
        float accA = 0.0f, accB = 0.0f;
#pragma unroll
        for (int kk = 0; kk < 48; ++kk) {
            int k = k0 + kk;
            float w = Wo[k * OUTF + o];
            accA = fmaf(s_cat[0][k], w, accA);
            accB = fmaf(s_cat[1][k], w, accB);
        }
        s_part[kseg][0][o] = accA;
        s_part[kseg][1][o] = accB;
        __syncthreads();
        if (tid < 128) {
            int qq = tid >> 6, oo = tid & 63;
            float acc = s_part[0][qq][oo] + s_part[1][qq][oo]
                      + s_part[2][qq][oo] + s_part[3][qq][oo] + bo[oo];
            out[(base + v0 + qq) * OUTF + oo] = tanhf(acc);
        }
    }
}

// ---------------------------------------------------------------------------
extern "C" void kernel_launch(void* const* d_in, const int* in_sizes, int n_in,
                              void* d_out, int out_size)
{
    const float* x  = (const float*)d_in[0];
    const float* Wf = (const float*)d_in[1];
    const float* bf = (const float*)d_in[2];
    const float* Ws = (const float*)d_in[3];
    const float* bs = (const float*)d_in[4];
    const float* Wo = (const float*)d_in[5];
    const float* bo = (const float*)d_in[6];
    float* out = (float*)d_out;

    prep_kernel<<<BB * VV, 64>>>(x, Wf, bf, Ws, bs);

    dim3 grid(VV / 2, BB);
    grav_kernel<<<grid, TPB>>>(x, Wo, bo, out);
}